// round 10
// baseline (speedup 1.0000x reference)
#include <cuda_runtime.h>
#include <cuda_bf16.h>
#include <math.h>

// UnitarySpectralFilter: psi [4096,4096,4] f32, alpha scalar f32.
// Analytic 4-point FFT -> unitary phase filter -> IFFT collapsed to a linear
// map per length-4 vector. Output layout decided at runtime from out_size
// (bench: real float32 mode). Pure HBM-streaming kernel at the DRAM roofline.
//
// Persistent grid-stride version: one wave of CTAs (152 SMs x 8 blocks),
// each looping over chunks -> no wave transitions, no repeated block launch.
// atan(log(|k|+eps)) computed on HOST; kernel does sincos(alpha*C_k) once.

static constexpr unsigned NVEC = 4096u * 4096u;   // number of length-4 vectors
static constexpr int THREADS = 256;
static constexpr int VEC_PER_THREAD = 4;
static constexpr unsigned CHUNK = THREADS * VEC_PER_THREAD;     // 1024 vectors
static constexpr unsigned NCHUNKS = NVEC / CHUNK;               // 16384
static constexpr unsigned BLOCKS = 152u * 8u;                   // 1216 (1 wave)

template <bool COMPLEX_OUT>
__global__ void __launch_bounds__(THREADS)
usf_kernel(const float4* __restrict__ in,
           const float* __restrict__ alpha_p,
           float4* __restrict__ out,
           float C0, float C1, float C2)   // atan(log(|k|+eps)) per freq
{
    // Coefficients: sincos of alpha*C_k, folded IFFT 1/4 scale. Once per thread.
    float alpha = __ldg(alpha_p);          // broadcast, L1-hit after warmup
    float s0, c0, s1, c1, s2, c2;
    __sincosf(alpha * C0, &s0, &c0);
    __sincosf(alpha * C1, &s1, &c1);
    __sincosf(alpha * C2, &s2, &c2);
    const float k0r = 0.25f * c0, k0i = 0.25f * s0;   // DC (X0)
    const float k1r = 0.50f * c1, k1i = 0.50f * s1;   // +/-1/4 pair, x2 folded
    const float k2r = 0.25f * c2, k2i = 0.25f * s2;   // Nyquist (X2)

    for (unsigned chunk = blockIdx.x; chunk < NCHUNKS; chunk += BLOCKS) {
        unsigned base = chunk * CHUNK + threadIdx.x;

        // Front-batch all data loads (MLP_p1 = VEC_PER_THREAD), evict-first
        float4 x[VEC_PER_THREAD];
#pragma unroll
        for (int j = 0; j < VEC_PER_THREAD; j++)
            x[j] = __ldcs(&in[base + j * THREADS]);

#pragma unroll
        for (int j = 0; j < VEC_PER_THREAD; j++) {
            unsigned idx = base + j * THREADS;
            float x0 = x[j].x, x1 = x[j].y, x2 = x[j].z, x3 = x[j].w;

            float e02 = x0 + x2, e13 = x1 + x3;
            float S = e02 + e13;          // X[0]
            float D = e02 - e13;          // X[2]
            float A = x0 - x2;            // Re X[1]
            float B = x3 - x1;            // Im X[1]

            float t0r = S * k0r, t0i = S * k0i;
            float t2r = D * k2r, t2i = D * k2i;
            float Er = t0r + t2r, Ei = t0i + t2i;   // even outputs base
            float Or = t0r - t2r, Oi = t0i - t2i;   // odd outputs base
            float ar = A * k1r, ai = A * k1i;
            float br = B * k1r, bi = B * k1i;

            if (COMPLEX_OUT) {
                __stcs(&out[2u * idx],
                       make_float4(Er + ar, Ei + ai, Or - br, Oi - bi));
                __stcs(&out[2u * idx + 1],
                       make_float4(Er - ar, Ei - ai, Or + br, Oi + bi));
            } else {
                // real parts only: (y0, y1, y2, y3)
                __stcs(&out[idx],
                       make_float4(Er + ar, Or - br, Er - ar, Or + br));
            }
        }
    }
}

extern "C" void kernel_launch(void* const* d_in, const int* in_sizes, int n_in,
                              void* d_out, int out_size)
{
    // psi = largest input, alpha = smallest (robust to ordering and to a
    // scalar reported as 0 or 1 elements).
    int psi_i = 0, alpha_i = 0;
    for (int i = 1; i < n_in; i++) {
        if (in_sizes[i] > in_sizes[psi_i])   psi_i = i;
        if (in_sizes[i] < in_sizes[alpha_i]) alpha_i = i;
    }
    const float4* psi   = (const float4*)d_in[psi_i];
    const float*  alpha = (const float*)d_in[alpha_i];
    float4*       out   = (float4*)d_out;

    long long psi_elems = (long long)in_sizes[psi_i];   // 67,108,864 floats

    // Host-side alpha-independent constants: atan(log(|k|+eps)),
    // fftfreq(4) = [0, .25, -.5, -.25], computed in float to match reference.
    const float EPS = 1e-8f;
    float C0 = atanf(logf(EPS));          // k = 0
    float C1 = atanf(logf(0.25f + EPS));  // |k| = 0.25 (pair)
    float C2 = atanf(logf(0.5f + EPS));   // |k| = 0.5  (Nyquist)

    if ((long long)out_size >= 2 * psi_elems) {
        usf_kernel<true><<<BLOCKS, THREADS>>>(psi, alpha, out, C0, C1, C2);
    } else {
        usf_kernel<false><<<BLOCKS, THREADS>>>(psi, alpha, out, C0, C1, C2);
    }
}

// round 11
// speedup vs baseline: 1.1232x; 1.1232x over previous
#include <cuda_runtime.h>
#include <cuda_bf16.h>
#include <math.h>

// UnitarySpectralFilter: psi [4096,4096,4] f32, alpha scalar f32.
// Analytic 4-point FFT -> unitary phase filter -> IFFT collapsed to a linear
// map per length-4 vector. Output layout decided at runtime from out_size
// (bench: real float32 mode). Pure HBM-streaming kernel at the DRAM roofline.
//
// Converged configuration (measured sweep):
//   flat grid 16384x256, VEC=4 (VEC=2: 78.1us, VEC=4: 74.6us, VEC=8: 76.3us,
//   persistent grid-stride: 81.3us), __ldcs/__stcs evict-first streaming,
//   host-side atan(log(|k|+eps)) constants, per-thread __sincosf (hidden
//   under DRAM stalls). Kernel ~74.6us @ 6.45 TB/s, DRAM 81.5%.

static constexpr unsigned NVEC = 4096u * 4096u;   // number of length-4 vectors
static constexpr int THREADS = 256;
static constexpr int VEC_PER_THREAD = 4;
static constexpr unsigned BLOCKS = NVEC / (THREADS * VEC_PER_THREAD);  // 16384

template <bool COMPLEX_OUT>
__global__ void __launch_bounds__(THREADS)
usf_kernel(const float4* __restrict__ in,
           const float* __restrict__ alpha_p,
           float4* __restrict__ out,
           float C0, float C1, float C2)   // atan(log(|k|+eps)) per freq
{
    unsigned base = blockIdx.x * (unsigned)(THREADS * VEC_PER_THREAD) + threadIdx.x;

    // Front-batch all data loads (MLP_p1 = VEC_PER_THREAD), evict-first
    float4 x[VEC_PER_THREAD];
#pragma unroll
    for (int j = 0; j < VEC_PER_THREAD; j++)
        x[j] = __ldcs(&in[base + j * THREADS]);

    // Coefficients: sincos of alpha*C_k, folded IFFT 1/4 scale.
    float alpha = __ldg(alpha_p);          // broadcast, L1-hit after warmup
    float s0, c0, s1, c1, s2, c2;
    __sincosf(alpha * C0, &s0, &c0);
    __sincosf(alpha * C1, &s1, &c1);
    __sincosf(alpha * C2, &s2, &c2);
    const float k0r = 0.25f * c0, k0i = 0.25f * s0;   // DC (X0)
    const float k1r = 0.50f * c1, k1i = 0.50f * s1;   // +/-1/4 pair, x2 folded
    const float k2r = 0.25f * c2, k2i = 0.25f * s2;   // Nyquist (X2)

#pragma unroll
    for (int j = 0; j < VEC_PER_THREAD; j++) {
        unsigned idx = base + j * THREADS;
        float x0 = x[j].x, x1 = x[j].y, x2 = x[j].z, x3 = x[j].w;

        float e02 = x0 + x2, e13 = x1 + x3;
        float S = e02 + e13;          // X[0]
        float D = e02 - e13;          // X[2]
        float A = x0 - x2;            // Re X[1]
        float B = x3 - x1;            // Im X[1]

        float t0r = S * k0r, t0i = S * k0i;
        float t2r = D * k2r, t2i = D * k2i;
        float Er = t0r + t2r, Ei = t0i + t2i;   // even outputs base
        float Or = t0r - t2r, Oi = t0i - t2i;   // odd outputs base
        float ar = A * k1r, ai = A * k1i;
        float br = B * k1r, bi = B * k1i;

        if (COMPLEX_OUT) {
            __stcs(&out[2u * idx],
                   make_float4(Er + ar, Ei + ai, Or - br, Oi - bi));
            __stcs(&out[2u * idx + 1],
                   make_float4(Er - ar, Ei - ai, Or + br, Oi + bi));
        } else {
            // real parts only: (y0, y1, y2, y3)
            __stcs(&out[idx], make_float4(Er + ar, Or - br, Er - ar, Or + br));
        }
    }
}

extern "C" void kernel_launch(void* const* d_in, const int* in_sizes, int n_in,
                              void* d_out, int out_size)
{
    // psi = largest input, alpha = smallest (robust to ordering and to a
    // scalar reported as 0 or 1 elements).
    int psi_i = 0, alpha_i = 0;
    for (int i = 1; i < n_in; i++) {
        if (in_sizes[i] > in_sizes[psi_i])   psi_i = i;
        if (in_sizes[i] < in_sizes[alpha_i]) alpha_i = i;
    }
    const float4* psi   = (const float4*)d_in[psi_i];
    const float*  alpha = (const float*)d_in[alpha_i];
    float4*       out   = (float4*)d_out;

    long long psi_elems = (long long)in_sizes[psi_i];   // 67,108,864 floats

    // Host-side alpha-independent constants: atan(log(|k|+eps)),
    // fftfreq(4) = [0, .25, -.5, -.25], computed in float to match reference.
    const float EPS = 1e-8f;
    float C0 = atanf(logf(EPS));          // k = 0
    float C1 = atanf(logf(0.25f + EPS));  // |k| = 0.25 (pair)
    float C2 = atanf(logf(0.5f + EPS));   // |k| = 0.5  (Nyquist)

    if ((long long)out_size >= 2 * psi_elems) {
        usf_kernel<true><<<BLOCKS, THREADS>>>(psi, alpha, out, C0, C1, C2);
    } else {
        usf_kernel<false><<<BLOCKS, THREADS>>>(psi, alpha, out, C0, C1, C2);
    }
}

// round 14
// speedup vs baseline: 1.1312x; 1.0071x over previous
#include <cuda_runtime.h>
#include <cuda_bf16.h>
#include <math.h>

// UnitarySpectralFilter: psi [4096,4096,4] f32, alpha scalar f32.
// Analytic 4-point FFT -> unitary phase filter -> IFFT collapsed to a linear
// map per length-4 vector. Output layout decided at runtime from out_size
// (bench: real float32 mode). Pure HBM-streaming kernel at the DRAM roofline.
//
// Sweep history (kernel time): VEC=2/256t: 78.1us, VEC=4/256t: 74.6-76.5us,
// VEC=8/256t: 76.3us, persistent: 81.3us. This round: VEC=4/512t (denser
// per-CTA address frontier, half the CTAs).

static constexpr unsigned NVEC = 4096u * 4096u;   // number of length-4 vectors
static constexpr int THREADS = 512;
static constexpr int VEC_PER_THREAD = 4;
static constexpr unsigned BLOCKS = NVEC / (THREADS * VEC_PER_THREAD);  // 8192

template <bool COMPLEX_OUT>
__global__ void __launch_bounds__(THREADS)
usf_kernel(const float4* __restrict__ in,
           const float* __restrict__ alpha_p,
           float4* __restrict__ out,
           float C0, float C1, float C2)   // atan(log(|k|+eps)) per freq
{
    unsigned base = blockIdx.x * (unsigned)(THREADS * VEC_PER_THREAD) + threadIdx.x;

    // Front-batch all data loads (MLP_p1 = VEC_PER_THREAD), evict-first
    float4 x[VEC_PER_THREAD];
#pragma unroll
    for (int j = 0; j < VEC_PER_THREAD; j++)
        x[j] = __ldcs(&in[base + j * THREADS]);

    // Coefficients: sincos of alpha*C_k, folded IFFT 1/4 scale.
    float alpha = __ldg(alpha_p);          // broadcast, L1-hit after warmup
    float s0, c0, s1, c1, s2, c2;
    __sincosf(alpha * C0, &s0, &c0);
    __sincosf(alpha * C1, &s1, &c1);
    __sincosf(alpha * C2, &s2, &c2);
    const float k0r = 0.25f * c0, k0i = 0.25f * s0;   // DC (X0)
    const float k1r = 0.50f * c1, k1i = 0.50f * s1;   // +/-1/4 pair, x2 folded
    const float k2r = 0.25f * c2, k2i = 0.25f * s2;   // Nyquist (X2)

#pragma unroll
    for (int j = 0; j < VEC_PER_THREAD; j++) {
        unsigned idx = base + j * THREADS;
        float x0 = x[j].x, x1 = x[j].y, x2 = x[j].z, x3 = x[j].w;

        float e02 = x0 + x2, e13 = x1 + x3;
        float S = e02 + e13;          // X[0]
        float D = e02 - e13;          // X[2]
        float A = x0 - x2;            // Re X[1]
        float B = x3 - x1;            // Im X[1]

        float t0r = S * k0r, t0i = S * k0i;
        float t2r = D * k2r, t2i = D * k2i;
        float Er = t0r + t2r, Ei = t0i + t2i;   // even outputs base
        float Or = t0r - t2r, Oi = t0i - t2i;   // odd outputs base
        float ar = A * k1r, ai = A * k1i;
        float br = B * k1r, bi = B * k1i;

        if (COMPLEX_OUT) {
            __stcs(&out[2u * idx],
                   make_float4(Er + ar, Ei + ai, Or - br, Oi - bi));
            __stcs(&out[2u * idx + 1],
                   make_float4(Er - ar, Ei - ai, Or + br, Oi + bi));
        } else {
            // real parts only: (y0, y1, y2, y3)
            __stcs(&out[idx], make_float4(Er + ar, Or - br, Er - ar, Or + br));
        }
    }
}

extern "C" void kernel_launch(void* const* d_in, const int* in_sizes, int n_in,
                              void* d_out, int out_size)
{
    // psi = largest input, alpha = smallest (robust to ordering and to a
    // scalar reported as 0 or 1 elements).
    int psi_i = 0, alpha_i = 0;
    for (int i = 1; i < n_in; i++) {
        if (in_sizes[i] > in_sizes[psi_i])   psi_i = i;
        if (in_sizes[i] < in_sizes[alpha_i]) alpha_i = i;
    }
    const float4* psi   = (const float4*)d_in[psi_i];
    const float*  alpha = (const float*)d_in[alpha_i];
    float4*       out   = (float4*)d_out;

    long long psi_elems = (long long)in_sizes[psi_i];   // 67,108,864 floats

    // Host-side alpha-independent constants: atan(log(|k|+eps)),
    // fftfreq(4) = [0, .25, -.5, -.25], computed in float to match reference.
    const float EPS = 1e-8f;
    float C0 = atanf(logf(EPS));          // k = 0
    float C1 = atanf(logf(0.25f + EPS));  // |k| = 0.25 (pair)
    float C2 = atanf(logf(0.5f + EPS));   // |k| = 0.5  (Nyquist)

    if ((long long)out_size >= 2 * psi_elems) {
        usf_kernel<true><<<BLOCKS, THREADS>>>(psi, alpha, out, C0, C1, C2);
    } else {
        usf_kernel<false><<<BLOCKS, THREADS>>>(psi, alpha, out, C0, C1, C2);
    }
}

// round 16
// speedup vs baseline: 1.1429x; 1.0103x over previous
#include <cuda_runtime.h>
#include <cuda_bf16.h>
#include <math.h>

// UnitarySpectralFilter: psi [4096,4096,4] f32, alpha scalar f32.
// Analytic 4-point FFT -> unitary phase filter -> IFFT collapsed to a linear
// map per length-4 vector. Output layout decided at runtime from out_size
// (bench: real float32 mode). Pure HBM-streaming kernel at the DRAM roofline.
//
// Sweep history (kernel time): VEC=2/256t 78.1, VEC=4/256t 74.6-76.5,
// VEC=8/256t 76.3, persistent 81.3, VEC=4/512t 74.5 (best, dur 81.47).
// This round: VEC=2/1024t — same 2048-vector CTA footprint as the best,
// more warps interleaving load/store at the SMSP arbiter.

static constexpr unsigned NVEC = 4096u * 4096u;   // number of length-4 vectors
static constexpr int THREADS = 1024;
static constexpr int VEC_PER_THREAD = 2;
static constexpr unsigned BLOCKS = NVEC / (THREADS * VEC_PER_THREAD);  // 8192

template <bool COMPLEX_OUT>
__global__ void __launch_bounds__(THREADS)
usf_kernel(const float4* __restrict__ in,
           const float* __restrict__ alpha_p,
           float4* __restrict__ out,
           float C0, float C1, float C2)   // atan(log(|k|+eps)) per freq
{
    unsigned base = blockIdx.x * (unsigned)(THREADS * VEC_PER_THREAD) + threadIdx.x;

    // Front-batch all data loads (MLP_p1 = VEC_PER_THREAD), evict-first
    float4 x[VEC_PER_THREAD];
#pragma unroll
    for (int j = 0; j < VEC_PER_THREAD; j++)
        x[j] = __ldcs(&in[base + j * THREADS]);

    // Coefficients: sincos of alpha*C_k, folded IFFT 1/4 scale.
    float alpha = __ldg(alpha_p);          // broadcast, L1-hit after warmup
    float s0, c0, s1, c1, s2, c2;
    __sincosf(alpha * C0, &s0, &c0);
    __sincosf(alpha * C1, &s1, &c1);
    __sincosf(alpha * C2, &s2, &c2);
    const float k0r = 0.25f * c0, k0i = 0.25f * s0;   // DC (X0)
    const float k1r = 0.50f * c1, k1i = 0.50f * s1;   // +/-1/4 pair, x2 folded
    const float k2r = 0.25f * c2, k2i = 0.25f * s2;   // Nyquist (X2)

#pragma unroll
    for (int j = 0; j < VEC_PER_THREAD; j++) {
        unsigned idx = base + j * THREADS;
        float x0 = x[j].x, x1 = x[j].y, x2 = x[j].z, x3 = x[j].w;

        float e02 = x0 + x2, e13 = x1 + x3;
        float S = e02 + e13;          // X[0]
        float D = e02 - e13;          // X[2]
        float A = x0 - x2;            // Re X[1]
        float B = x3 - x1;            // Im X[1]

        float t0r = S * k0r, t0i = S * k0i;
        float t2r = D * k2r, t2i = D * k2i;
        float Er = t0r + t2r, Ei = t0i + t2i;   // even outputs base
        float Or = t0r - t2r, Oi = t0i - t2i;   // odd outputs base
        float ar = A * k1r, ai = A * k1i;
        float br = B * k1r, bi = B * k1i;

        if (COMPLEX_OUT) {
            __stcs(&out[2u * idx],
                   make_float4(Er + ar, Ei + ai, Or - br, Oi - bi));
            __stcs(&out[2u * idx + 1],
                   make_float4(Er - ar, Ei - ai, Or + br, Oi + bi));
        } else {
            // real parts only: (y0, y1, y2, y3)
            __stcs(&out[idx], make_float4(Er + ar, Or - br, Er - ar, Or + br));
        }
    }
}

extern "C" void kernel_launch(void* const* d_in, const int* in_sizes, int n_in,
                              void* d_out, int out_size)
{
    // psi = largest input, alpha = smallest (robust to ordering and to a
    // scalar reported as 0 or 1 elements).
    int psi_i = 0, alpha_i = 0;
    for (int i = 1; i < n_in; i++) {
        if (in_sizes[i] > in_sizes[psi_i])   psi_i = i;
        if (in_sizes[i] < in_sizes[alpha_i]) alpha_i = i;
    }
    const float4* psi   = (const float4*)d_in[psi_i];
    const float*  alpha = (const float*)d_in[alpha_i];
    float4*       out   = (float4*)d_out;

    long long psi_elems = (long long)in_sizes[psi_i];   // 67,108,864 floats

    // Host-side alpha-independent constants: atan(log(|k|+eps)),
    // fftfreq(4) = [0, .25, -.5, -.25], computed in float to match reference.
    const float EPS = 1e-8f;
    float C0 = atanf(logf(EPS));          // k = 0
    float C1 = atanf(logf(0.25f + EPS));  // |k| = 0.25 (pair)
    float C2 = atanf(logf(0.5f + EPS));   // |k| = 0.5  (Nyquist)

    if ((long long)out_size >= 2 * psi_elems) {
        usf_kernel<true><<<BLOCKS, THREADS>>>(psi, alpha, out, C0, C1, C2);
    } else {
        usf_kernel<false><<<BLOCKS, THREADS>>>(psi, alpha, out, C0, C1, C2);
    }
}